// round 11
// baseline (speedup 1.0000x reference)
#include <cuda_runtime.h>
#include <cuda_bf16.h>
#include <math.h>
#include <stdint.h>

#define LL 2048
#define DD 64
#define HH 8
#define KSPLIT 2
#define KHALF (LL / KSPLIT)

// Per-(head,key) folded bias coefficients (see prep_kernel)
__device__ float g_xy[HH][LL][12];
// Per-(split,head,query) partial softmax stats: (row_max, sum_exp)
__device__ float2 g_pstats[KSPLIT][HH][LL];
// Partial outputs per k-split
__device__ float g_pout[KSPLIT][HH * LL * DD];
// Preconverted bf16 hi/lo operands
__device__ __nv_bfloat16 gQh[HH * LL * DD], gQl[HH * LL * DD];
__device__ __nv_bfloat16 gKh[HH * LL * DD], gKl[HH * LL * DD];
__device__ __nv_bfloat16 gVh[HH * LL * DD], gVl[HH * LL * DD];

// ---------------------------------------------------------------------------
__device__ __forceinline__ uint32_t smem_u32(const void* p) {
    return (uint32_t)__cvta_generic_to_shared(p);
}
__device__ __forceinline__ void cp16(void* s, const void* g) {
    asm volatile("cp.async.cg.shared.global [%0], [%1], 16;" ::
                 "r"(smem_u32(s)), "l"(g));
}
__device__ __forceinline__ void cp_commit() {
    asm volatile("cp.async.commit_group;" ::: "memory");
}
__device__ __forceinline__ void cp_wait1() {
    asm volatile("cp.async.wait_group 1;" ::: "memory");
}
__device__ __forceinline__ void cp_wait0() {
    asm volatile("cp.async.wait_group 0;" ::: "memory");
}
__device__ __forceinline__ void ldsm_x4(uint32_t a, uint32_t& r0, uint32_t& r1,
                                        uint32_t& r2, uint32_t& r3) {
    asm volatile("ldmatrix.sync.aligned.m8n8.x4.shared.b16 {%0,%1,%2,%3}, [%4];"
                 : "=r"(r0), "=r"(r1), "=r"(r2), "=r"(r3) : "r"(a));
}
__device__ __forceinline__ void ldsm_x2(uint32_t a, uint32_t& r0, uint32_t& r1) {
    asm volatile("ldmatrix.sync.aligned.m8n8.x2.shared.b16 {%0,%1}, [%2];"
                 : "=r"(r0), "=r"(r1) : "r"(a));
}
__device__ __forceinline__ void ldsm_x2t(uint32_t a, uint32_t& r0, uint32_t& r1) {
    asm volatile("ldmatrix.sync.aligned.m8n8.x2.trans.shared.b16 {%0,%1}, [%2];"
                 : "=r"(r0), "=r"(r1) : "r"(a));
}
__device__ __forceinline__ void mma16816(float* d, const uint32_t* a, const uint32_t* b) {
    asm volatile(
        "mma.sync.aligned.m16n8k16.row.col.f32.bf16.bf16.f32 "
        "{%0,%1,%2,%3}, {%4,%5,%6,%7}, {%8,%9}, {%0,%1,%2,%3};"
        : "+f"(d[0]), "+f"(d[1]), "+f"(d[2]), "+f"(d[3])
        : "r"(a[0]), "r"(a[1]), "r"(a[2]), "r"(a[3]), "r"(b[0]), "r"(b[1]));
}
__device__ __forceinline__ void split2(float x, __nv_bfloat16& hi, __nv_bfloat16& lo) {
    hi = __float2bfloat16(x);
    lo = __float2bfloat16(x - __bfloat162float(hi));
}
__device__ __forceinline__ uint32_t bfpack(float x, float y, uint32_t& lo) {
    __nv_bfloat16 hx, lx, hy, ly;
    split2(x, hx, lx);
    split2(y, hy, ly);
    __nv_bfloat162 H; H.x = hx; H.y = hy;
    __nv_bfloat162 L; L.x = lx; L.y = ly;
    lo = *(uint32_t*)&L;
    return *(uint32_t*)&H;
}
__device__ __forceinline__ float bias_apply(float accv, float d0, float d1, float d2,
                                            float rtv, float rbv,
                                            float4 x0, float4 x1, float4 x2) {
    float x  = d0 * x0.x + d1 * x0.y + d2 * x0.z + x0.w + rtv * x1.x + rbv * x1.y;
    float bb = d0 * x1.z + d1 * x1.w + d2 * x2.x + x2.y + rtv * x2.z + rbv * x2.w;
    float w = (x > 15.f) ? x : __logf(1.f + __expf(x));
    return accv * w + bb;
}
// combine two partial (m, s) stats -> (m, 1/s)
__device__ __forceinline__ float2 stat_combine(float2 a, float2 b) {
    float m = fmaxf(a.x, b.x);
    float s = a.y * __expf(a.x - m) + b.y * __expf(b.x - m);
    return make_float2(m, 1.f / s);
}

// ---------------------------------------------------------------------------
// Kernel P: per-(h,k) coefficient fold (includes Ww/Wb columns).
// ---------------------------------------------------------------------------
__global__ void prep_kernel(const float* __restrict__ dkt,
                            const float* __restrict__ dkb,
                            const float* __restrict__ dks,
                            const float* __restrict__ Ww,
                            const float* __restrict__ Wb) {
    int idx = blockIdx.x * blockDim.x + threadIdx.x;
    if (idx >= HH * LL) return;
    int h = idx >> 11, k = idx & (LL - 1);
    const float* s0 = dks + k * 8;
    const float* s1 = s0 + 4;
    float* o = g_xy[h][k];
    float X3 = 0.f, Y3 = 0.f;
#pragma unroll
    for (int f = 0; f < 3; f++) {
        float A = s0[f] + s1[f];
        float B = dkt[k * 3 + f] * s0[f] + dkb[k * 3 + f] * s1[f];
        float wwf = Ww[f * HH + h], wbf = Wb[f * HH + h];
        o[f] = A * wwf;
        o[6 + f] = A * wbf;
        X3 -= B * wwf;
        Y3 -= B * wbf;
    }
    float ww3 = Ww[3 * HH + h], wb3 = Wb[3 * HH + h];
    o[3] = X3;            o[9]  = Y3;
    o[4] = s0[3] * ww3;   o[5]  = s1[3] * ww3;
    o[10] = s0[3] * wb3;  o[11] = s1[3] * wb3;
}

// ---------------------------------------------------------------------------
// Kernel Conv: fp32 Q(K,V) -> bf16 hi/lo split arrays (Q scaled by 1/8).
// ---------------------------------------------------------------------------
__global__ void conv_kernel(const float* __restrict__ q,
                            const float* __restrict__ k,
                            const float* __restrict__ v) {
    size_t base = ((size_t)blockIdx.x * 256 + threadIdx.x) * 4;
    if (base >= (size_t)HH * LL * DD) return;

    float4 a = *(const float4*)(q + base);
    uint32_t l0, l1, h0, h1;
    h0 = bfpack(a.x * 0.125f, a.y * 0.125f, l0);
    h1 = bfpack(a.z * 0.125f, a.w * 0.125f, l1);
    *(uint2*)&gQh[base] = make_uint2(h0, h1);
    *(uint2*)&gQl[base] = make_uint2(l0, l1);

    a = *(const float4*)(k + base);
    h0 = bfpack(a.x, a.y, l0);
    h1 = bfpack(a.z, a.w, l1);
    *(uint2*)&gKh[base] = make_uint2(h0, h1);
    *(uint2*)&gKl[base] = make_uint2(l0, l1);

    a = *(const float4*)(v + base);
    h0 = bfpack(a.x, a.y, l0);
    h1 = bfpack(a.z, a.w, l1);
    *(uint2*)&gVh[base] = make_uint2(h0, h1);
    *(uint2*)&gVl[base] = make_uint2(l0, l1);
}

// ---------------------------------------------------------------------------
// Kernel A: raw scores + partial softmax stats for one k-half.
// Block: 64(q) x 32(k-tile), 8 warps as 4(m) x 2(n); blockIdx.z = k-split.
// ---------------------------------------------------------------------------
__global__ __launch_bounds__(256) void scores_kernel(
    const float* __restrict__ dq, const float* __restrict__ rt,
    const float* __restrict__ rb, float* __restrict__ scores) {
    __shared__ __align__(16) __nv_bfloat16 Qh[64][72], Ql[64][72];
    __shared__ __align__(16) __nv_bfloat16 Kh[2][32][72], Kl[2][32][72];
    __shared__ __align__(16) float Xs[2][32][12];
    __shared__ float Dq[64][4];
    __shared__ float SredM[8][16], SredS[8][16];

    const int h = blockIdx.y, qt = blockIdx.x * 64;
    const int split = blockIdx.z, koff = split * KHALF;
    const int t = threadIdx.x, lane = t & 31, warp = t >> 5;
    const int m0 = (warp >> 1) * 16, n0 = (warp & 1) * 16;

    // issue preload of K tile 0 (at koff)
    {
        int r = t >> 3, cc = (t & 7) * 8;
        size_t g = ((size_t)h * LL + koff + r) * DD + cc;
        cp16(&Kh[0][r][cc], &gKh[g]);
        cp16(&Kl[0][r][cc], &gKl[g]);
        if (t < 96) cp16(&Xs[0][t / 3][(t % 3) * 4], &g_xy[h][koff + t / 3][(t % 3) * 4]);
    }
    cp_commit();

    // Q tile from preconverted arrays (plain loads)
    for (int i = t; i < 64 * 8; i += 256) {
        int r = i >> 3, c8 = (i & 7) * 8;
        size_t g = ((size_t)h * LL + qt + r) * DD + c8;
        *(uint4*)&Qh[r][c8] = *(const uint4*)&gQh[g];
        *(uint4*)&Ql[r][c8] = *(const uint4*)&gQl[g];
    }
    for (int i = t; i < 64 * 3; i += 256) Dq[i / 3][i % 3] = dq[(qt + i / 3) * 3 + i % 3];
    __syncthreads();

    const int r0l = m0 + (lane >> 2), r1l = r0l + 8;
    const float da0 = Dq[r0l][0], da1 = Dq[r0l][1], da2 = Dq[r0l][2];
    const float db0 = Dq[r1l][0], db1 = Dq[r1l][1], db2 = Dq[r1l][2];
    const int qg0 = qt + r0l, qg1 = qt + r1l;

    float m0r = -1e30f, s0r = 0.f, m1r = -1e30f, s1r = 0.f;

    for (int ti = 0; ti < 32; ti++) {
        const int cur = ti & 1, kt = koff + ti * 32;
        if (ti < 31) {
            int nb = cur ^ 1, nkt = kt + 32;
            int r = t >> 3, cc = (t & 7) * 8;
            size_t g = ((size_t)h * LL + nkt + r) * DD + cc;
            cp16(&Kh[nb][r][cc], &gKh[g]);
            cp16(&Kl[nb][r][cc], &gKl[g]);
            if (t < 96) cp16(&Xs[nb][t / 3][(t % 3) * 4], &g_xy[h][nkt + t / 3][(t % 3) * 4]);
            cp_commit();
            cp_wait1();
        } else {
            cp_wait0();
        }
        __syncthreads();

        // prefetch rt/rb for this tile's epilogue
        float2 prtA[2], prbA[2], prtB[2], prbB[2];
#pragma unroll
        for (int nt = 0; nt < 2; nt++) {
            int kg = kt + n0 + nt * 8 + (lane & 3) * 2;
            prtA[nt] = *(const float2*)(rt + (size_t)qg0 * LL + kg);
            prbA[nt] = *(const float2*)(rb + (size_t)qg0 * LL + kg);
            prtB[nt] = *(const float2*)(rt + (size_t)qg1 * LL + kg);
            prbB[nt] = *(const float2*)(rb + (size_t)qg1 * LL + kg);
        }

        float acc[2][4];
#pragma unroll
        for (int nt = 0; nt < 2; nt++)
#pragma unroll
            for (int j = 0; j < 4; j++) acc[nt][j] = 0.f;

#pragma unroll
        for (int s = 0; s < 4; s++) {
            uint32_t ah[4], al[4];
            int ar = m0 + (lane & 15), ac = s * 16 + (lane >> 4) * 8;
            ldsm_x4(smem_u32(&Qh[ar][ac]), ah[0], ah[1], ah[2], ah[3]);
            ldsm_x4(smem_u32(&Ql[ar][ac]), al[0], al[1], al[2], al[3]);
#pragma unroll
            for (int nt = 0; nt < 2; nt++) {
                uint32_t bh[2], bl[2];
                int br = n0 + nt * 8 + (lane & 7);
                int bc = s * 16 + ((lane >> 3) & 1) * 8;
                ldsm_x2(smem_u32(&Kh[cur][br][bc]), bh[0], bh[1]);
                ldsm_x2(smem_u32(&Kl[cur][br][bc]), bl[0], bl[1]);
                mma16816(acc[nt], ah, bh);
                mma16816(acc[nt], ah, bl);
                mma16816(acc[nt], al, bh);
            }
        }

        // Epilogue: bias + softplus gate + write + stats
        float v0[4], v1[4];
#pragma unroll
        for (int nt = 0; nt < 2; nt++) {
            int kc = n0 + nt * 8 + (lane & 3) * 2;
            int kg = kt + kc;
            float4 xa0 = *(const float4*)&Xs[cur][kc][0];
            float4 xa1 = *(const float4*)&Xs[cur][kc][4];
            float4 xa2 = *(const float4*)&Xs[cur][kc][8];
            float4 xb0 = *(const float4*)&Xs[cur][kc + 1][0];
            float4 xb1 = *(const float4*)&Xs[cur][kc + 1][4];
            float4 xb2 = *(const float4*)&Xs[cur][kc + 1][8];

            float s00 = bias_apply(acc[nt][0], da0, da1, da2, prtA[nt].x, prbA[nt].x, xa0, xa1, xa2);
            float s01 = bias_apply(acc[nt][1], da0, da1, da2, prtA[nt].y, prbA[nt].y, xb0, xb1, xb2);
            float s10 = bias_apply(acc[nt][2], db0, db1, db2, prtB[nt].x, prbB[nt].x, xa0, xa1, xa2);
            float s11 = bias_apply(acc[nt][3], db0, db1, db2, prtB[nt].y, prbB[nt].y, xb0, xb1, xb2);

            v0[nt * 2] = s00; v0[nt * 2 + 1] = s01;
            v1[nt * 2] = s10; v1[nt * 2 + 1] = s11;

            *(float2*)(scores + ((size_t)(h * LL) + qg0) * LL + kg) = make_float2(s00, s01);
            *(float2*)(scores + ((size_t)(h * LL) + qg1) * LL + kg) = make_float2(s10, s11);
        }

        float tm0 = fmaxf(fmaxf(v0[0], v0[1]), fmaxf(v0[2], v0[3]));
        float tm1 = fmaxf(fmaxf(v1[0], v1[1]), fmaxf(v1[2], v1[3]));
        float nm0 = fmaxf(m0r, tm0), nm1 = fmaxf(m1r, tm1);
        float ad0 = 0.f, ad1 = 0.f;
#pragma unroll
        for (int j = 0; j < 4; j++) {
            ad0 += __expf(v0[j] - nm0);
            ad1 += __expf(v1[j] - nm1);
        }
        s0r = s0r * __expf(m0r - nm0) + ad0; m0r = nm0;
        s1r = s1r * __expf(m1r - nm1) + ad1; m1r = nm1;

        __syncthreads();
    }

    // Stats reduction: across lane&3, then warp pairs
#pragma unroll
    for (int off = 1; off <= 2; off <<= 1) {
        float om = __shfl_xor_sync(0xffffffffu, m0r, off);
        float os = __shfl_xor_sync(0xffffffffu, s0r, off);
        float nm = fmaxf(m0r, om);
        s0r = s0r * __expf(m0r - nm) + os * __expf(om - nm);
        m0r = nm;
        om = __shfl_xor_sync(0xffffffffu, m1r, off);
        os = __shfl_xor_sync(0xffffffffu, s1r, off);
        nm = fmaxf(m1r, om);
        s1r = s1r * __expf(m1r - nm) + os * __expf(om - nm);
        m1r = nm;
    }
    if ((lane & 3) == 0) {
        int lr = lane >> 2;
        SredM[warp][lr] = m0r;     SredS[warp][lr] = s0r;
        SredM[warp][8 + lr] = m1r; SredS[warp][8 + lr] = s1r;
    }
    __syncthreads();
    if (t < 64) {
        int wp = t >> 4, loc = t & 15;
        float mA = SredM[2 * wp][loc], sA = SredS[2 * wp][loc];
        float mB = SredM[2 * wp + 1][loc], sB = SredS[2 * wp + 1][loc];
        float nm = fmaxf(mA, mB);
        float ss = sA * __expf(mA - nm) + sB * __expf(mB - nm);
        g_pstats[split][h][qt + t] = make_float2(nm, ss);  // raw (m, sum)
    }
}

// ---------------------------------------------------------------------------
// Kernel C: fused softmax + PV over one k-half; partial out -> g_pout[split].
// Block: 128(q) x 64(d), 8 warps each owning m16 x n64; blockIdx.z = k-split.
// ---------------------------------------------------------------------------
__global__ __launch_bounds__(256) void smpv_kernel(const float* __restrict__ c,
                                                   float* __restrict__ probs) {
    __shared__ __align__(16) __nv_bfloat16 Vh[2][64][72], Vl[2][64][72];
    __shared__ __align__(16) float Cs[2048];

    const int h = blockIdx.y, qt = blockIdx.x * 128;
    const int split = blockIdx.z, koff = split * KHALF;
    const int t = threadIdx.x, lane = t & 31, warp = t >> 5;
    const int c0 = (lane & 3) * 2;
    const int r0 = qt + warp * 16 + (lane >> 2);

    float* sp0 = probs + ((size_t)h * LL + r0) * LL;
    float* sp1 = sp0 + 8 * LL;  // row r0+8

    const float2 st0 = stat_combine(g_pstats[0][h][r0], g_pstats[1][h][r0]);
    const float2 st1 = stat_combine(g_pstats[0][h][r0 + 8], g_pstats[1][h][r0 + 8]);

    // V tile 0 preload (at koff): 64 rows x 64 cols = 512 cp16 per array
#pragma unroll
    for (int j = 0; j < 2; j++) {
        int i = t + j * 256;
        int r = i >> 3, ce = (i & 7) * 8;
        size_t g = ((size_t)h * LL + koff + r) * DD + ce;
        cp16(&Vh[0][r][ce], &gVh[g]);
        cp16(&Vl[0][r][ce], &gVl[g]);
    }
    cp_commit();

    // c -> smem
    for (int i = t; i < 512; i += 256)
        *(float4*)&Cs[i * 4] = *(const float4*)(c + i * 4);

    // prefetch scores tile 0
    float2 pre[16];
#pragma unroll
    for (int s = 0; s < 4; s++) {
        int col = koff + s * 16 + c0;
        pre[s * 4 + 0] = *(const float2*)(sp0 + col);
        pre[s * 4 + 1] = *(const float2*)(sp1 + col);
        pre[s * 4 + 2] = *(const float2*)(sp0 + col + 8);
        pre[s * 4 + 3] = *(const float2*)(sp1 + col + 8);
    }

    float acc[8][4];
#pragma unroll
    for (int nt = 0; nt < 8; nt++)
#pragma unroll
        for (int j = 0; j < 4; j++) acc[nt][j] = 0.f;

    const int NT = KHALF / 64;  // 16 tiles
    for (int ti = 0; ti < NT; ti++) {
        const int cur = ti & 1, kt = koff + ti * 64;
        if (ti < NT - 1) {
            int nb = cur ^ 1, nkt = kt + 64;
#pragma unroll
            for (int j = 0; j < 2; j++) {
                int i = t + j * 256;
                int r = i >> 3, ce = (i & 7) * 8;
                size_t g = ((size_t)h * LL + nkt + r) * DD + ce;
                cp16(&Vh[nb][r][ce], &gVh[g]);
                cp16(&Vl[nb][r][ce], &gVl[g]);
            }
            cp_commit();
            cp_wait1();
        } else {
            cp_wait0();
        }
        __syncthreads();

        // transform prefetched scores -> probs writes + A fragments
        uint32_t AH[4][4], AL[4][4];
#pragma unroll
        for (int s = 0; s < 4; s++) {
            int col = kt + s * 16 + c0;
            float2 cA = *(const float2*)&Cs[col];
            float2 cB = *(const float2*)&Cs[col + 8];
            float p00 = __expf(pre[s * 4 + 0].x - st0.x) * st0.y * cA.x;
            float p01 = __expf(pre[s * 4 + 0].y - st0.x) * st0.y * cA.y;
            float p10 = __expf(pre[s * 4 + 1].x - st1.x) * st1.y * cA.x;
            float p11 = __expf(pre[s * 4 + 1].y - st1.x) * st1.y * cA.y;
            float p20 = __expf(pre[s * 4 + 2].x - st0.x) * st0.y * cB.x;
            float p21 = __expf(pre[s * 4 + 2].y - st0.x) * st0.y * cB.y;
            float p30 = __expf(pre[s * 4 + 3].x - st1.x) * st1.y * cB.x;
            float p31 = __expf(pre[s * 4 + 3].y - st1.x) * st1.y * cB.y;

            *(float2*)(sp0 + col)     = make_float2(p00, p01);
            *(float2*)(sp1 + col)     = make_float2(p10, p11);
            *(float2*)(sp0 + col + 8) = make_float2(p20, p21);
            *(float2*)(sp1 + col + 8) = make_float2(p30, p31);

            AH[s][0] = bfpack(p00, p01, AL[s][0]);
            AH[s][1] = bfpack(p10, p11, AL[s][1]);
            AH[s][2] = bfpack(p20, p21, AL[s][2]);
            AH[s][3] = bfpack(p30, p31, AL[s][3]);
        }

        // prefetch scores for next tile (hidden under MMAs)
        if (ti < NT - 1) {
            int nkt = kt + 64;
#pragma unroll
            for (int s = 0; s < 4; s++) {
                int col = nkt + s * 16 + c0;
                pre[s * 4 + 0] = *(const float2*)(sp0 + col);
                pre[s * 4 + 1] = *(const float2*)(sp1 + col);
                pre[s * 4 + 2] = *(const float2*)(sp0 + col + 8);
                pre[s * 4 + 3] = *(const float2*)(sp1 + col + 8);
            }
        }

        // MMAs: m16 x n64 per warp
#pragma unroll
        for (int s = 0; s < 4; s++) {
            int vr = s * 16 + (lane & 7) + ((lane >> 3) & 1) * 8;
#pragma unroll
            for (int nt = 0; nt < 8; nt++) {
                uint32_t bh[2], bl[2];
                int vc = nt * 8;
                ldsm_x2t(smem_u32(&Vh[cur][vr][vc]), bh[0], bh[1]);
                ldsm_x2t(smem_u32(&Vl[cur][vr][vc]), bl[0], bl[1]);
                mma16816(acc[nt], AH[s], bh);
                mma16816(acc[nt], AH[s], bl);
                mma16816(acc[nt], AL[s], bh);
            }
        }
        __syncthreads();
    }

    // Partial output: 16 rows x 64 cols per warp
    float* po = g_pout[split];
#pragma unroll
    for (int nt = 0; nt < 8; nt++) {
        int dc = nt * 8 + c0;
        *(float2*)(po + ((size_t)h * LL + r0) * DD + dc) =
            make_float2(acc[nt][0], acc[nt][1]);
        *(float2*)(po + ((size_t)h * LL + r0 + 8) * DD + dc) =
            make_float2(acc[nt][2], acc[nt][3]);
    }
}

// ---------------------------------------------------------------------------
// Kernel R: out = g_pout[0] + g_pout[1]
// ---------------------------------------------------------------------------
__global__ void reduce_kernel(float* __restrict__ out) {
    size_t i = ((size_t)blockIdx.x * 256 + threadIdx.x) * 4;
    if (i >= (size_t)HH * LL * DD) return;
    float4 a = *(const float4*)&g_pout[0][i];
    float4 b = *(const float4*)&g_pout[1][i];
    *(float4*)(out + i) = make_float4(a.x + b.x, a.y + b.y, a.z + b.z, a.w + b.w);
}

// ---------------------------------------------------------------------------
extern "C" void kernel_launch(void* const* d_in, const int* in_sizes, int n_in,
                              void* d_out, int out_size) {
    const float* q   = (const float*)d_in[0];
    const float* k   = (const float*)d_in[1];
    const float* v   = (const float*)d_in[2];
    const float* c   = (const float*)d_in[3];
    const float* dq  = (const float*)d_in[4];
    const float* dkt = (const float*)d_in[5];
    const float* dkb = (const float*)d_in[6];
    const float* dks = (const float*)d_in[7];
    const float* rt  = (const float*)d_in[8];
    const float* rb  = (const float*)d_in[9];
    const float* Ww  = (const float*)d_in[10];
    const float* Wb  = (const float*)d_in[11];

    float* out   = (float*)d_out;                        // [H, L, D]
    float* probs = (float*)d_out + (size_t)HH * LL * DD; // [H, L, L]

    prep_kernel<<<(HH * LL) / 256, 256>>>(dkt, dkb, dks, Ww, Wb);
    conv_kernel<<<(HH * LL * DD) / (256 * 4), 256>>>(q, k, v);

    dim3 gridA(LL / 64, HH, KSPLIT);
    scores_kernel<<<gridA, 256>>>(dq, rt, rb, probs);

    dim3 gridC(LL / 128, HH, KSPLIT);
    smpv_kernel<<<gridC, 256>>>(c, probs);

    reduce_kernel<<<(HH * LL * DD) / (256 * 4), 256>>>(out);
}

// round 13
// speedup vs baseline: 1.2611x; 1.2611x over previous
#include <cuda_runtime.h>
#include <cuda_bf16.h>
#include <math.h>
#include <stdint.h>

#define LL 2048
#define DD 64
#define HH 8

// Per-(head,key) folded bias coefficients (see prep_kernel)
__device__ float g_xy[HH][LL][12];
// Per-(head,query) softmax stats: (row_max, 1/sum_exp)
__device__ float2 g_stats[HH][LL];
// Preconverted bf16 hi/lo operands
__device__ __nv_bfloat16 gQh[HH * LL * DD], gQl[HH * LL * DD];
__device__ __nv_bfloat16 gKh[HH * LL * DD], gKl[HH * LL * DD];
__device__ __nv_bfloat16 gVh[HH * LL * DD], gVl[HH * LL * DD];

// ---------------------------------------------------------------------------
__device__ __forceinline__ uint32_t smem_u32(const void* p) {
    return (uint32_t)__cvta_generic_to_shared(p);
}
__device__ __forceinline__ void cp16(void* s, const void* g) {
    asm volatile("cp.async.cg.shared.global [%0], [%1], 16;" ::
                 "r"(smem_u32(s)), "l"(g));
}
__device__ __forceinline__ void cp_commit() {
    asm volatile("cp.async.commit_group;" ::: "memory");
}
__device__ __forceinline__ void cp_wait1() {
    asm volatile("cp.async.wait_group 1;" ::: "memory");
}
__device__ __forceinline__ void cp_wait0() {
    asm volatile("cp.async.wait_group 0;" ::: "memory");
}
__device__ __forceinline__ void ldsm_x4(uint32_t a, uint32_t& r0, uint32_t& r1,
                                        uint32_t& r2, uint32_t& r3) {
    asm volatile("ldmatrix.sync.aligned.m8n8.x4.shared.b16 {%0,%1,%2,%3}, [%4];"
                 : "=r"(r0), "=r"(r1), "=r"(r2), "=r"(r3) : "r"(a));
}
__device__ __forceinline__ void ldsm_x2(uint32_t a, uint32_t& r0, uint32_t& r1) {
    asm volatile("ldmatrix.sync.aligned.m8n8.x2.shared.b16 {%0,%1}, [%2];"
                 : "=r"(r0), "=r"(r1) : "r"(a));
}
__device__ __forceinline__ void ldsm_x4t(uint32_t a, uint32_t& r0, uint32_t& r1,
                                         uint32_t& r2, uint32_t& r3) {
    asm volatile("ldmatrix.sync.aligned.m8n8.x4.trans.shared.b16 {%0,%1,%2,%3}, [%4];"
                 : "=r"(r0), "=r"(r1), "=r"(r2), "=r"(r3) : "r"(a));
}
__device__ __forceinline__ void mma16816(float* d, const uint32_t* a, const uint32_t* b) {
    asm volatile(
        "mma.sync.aligned.m16n8k16.row.col.f32.bf16.bf16.f32 "
        "{%0,%1,%2,%3}, {%4,%5,%6,%7}, {%8,%9}, {%0,%1,%2,%3};"
        : "+f"(d[0]), "+f"(d[1]), "+f"(d[2]), "+f"(d[3])
        : "r"(a[0]), "r"(a[1]), "r"(a[2]), "r"(a[3]), "r"(b[0]), "r"(b[1]));
}
__device__ __forceinline__ void split2(float x, __nv_bfloat16& hi, __nv_bfloat16& lo) {
    hi = __float2bfloat16(x);
    lo = __float2bfloat16(x - __bfloat162float(hi));
}
__device__ __forceinline__ uint32_t bfpack(float x, float y, uint32_t& lo) {
    __nv_bfloat16 hx, lx, hy, ly;
    split2(x, hx, lx);
    split2(y, hy, ly);
    __nv_bfloat162 H; H.x = hx; H.y = hy;
    __nv_bfloat162 L; L.x = lx; L.y = ly;
    lo = *(uint32_t*)&L;
    return *(uint32_t*)&H;
}
__device__ __forceinline__ float bias_apply(float accv, float d0, float d1, float d2,
                                            float rtv, float rbv,
                                            float4 x0, float4 x1, float4 x2) {
    float x  = d0 * x0.x + d1 * x0.y + d2 * x0.z + x0.w + rtv * x1.x + rbv * x1.y;
    float bb = d0 * x1.z + d1 * x1.w + d2 * x2.x + x2.y + rtv * x2.z + rbv * x2.w;
    float w = (x > 15.f) ? x : __logf(1.f + __expf(x));
    return accv * w + bb;
}

// ---------------------------------------------------------------------------
// Kernel P: per-(h,k) coefficient fold (includes Ww/Wb columns).
// ---------------------------------------------------------------------------
__global__ void prep_kernel(const float* __restrict__ dkt,
                            const float* __restrict__ dkb,
                            const float* __restrict__ dks,
                            const float* __restrict__ Ww,
                            const float* __restrict__ Wb) {
    int idx = blockIdx.x * blockDim.x + threadIdx.x;
    if (idx >= HH * LL) return;
    int h = idx >> 11, k = idx & (LL - 1);
    const float* s0 = dks + k * 8;
    const float* s1 = s0 + 4;
    float* o = g_xy[h][k];
    float X3 = 0.f, Y3 = 0.f;
#pragma unroll
    for (int f = 0; f < 3; f++) {
        float A = s0[f] + s1[f];
        float B = dkt[k * 3 + f] * s0[f] + dkb[k * 3 + f] * s1[f];
        float wwf = Ww[f * HH + h], wbf = Wb[f * HH + h];
        o[f] = A * wwf;
        o[6 + f] = A * wbf;
        X3 -= B * wwf;
        Y3 -= B * wbf;
    }
    float ww3 = Ww[3 * HH + h], wb3 = Wb[3 * HH + h];
    o[3] = X3;            o[9]  = Y3;
    o[4] = s0[3] * ww3;   o[5]  = s1[3] * ww3;
    o[10] = s0[3] * wb3;  o[11] = s1[3] * wb3;
}

// ---------------------------------------------------------------------------
// Kernel Conv: fp32 Q(K,V) -> bf16 hi/lo split arrays (Q scaled by 1/8).
// ---------------------------------------------------------------------------
__global__ void conv_kernel(const float* __restrict__ q,
                            const float* __restrict__ k,
                            const float* __restrict__ v) {
    size_t base = ((size_t)blockIdx.x * 256 + threadIdx.x) * 4;
    if (base >= (size_t)HH * LL * DD) return;

    float4 a = *(const float4*)(q + base);
    uint32_t l0, l1, h0, h1;
    h0 = bfpack(a.x * 0.125f, a.y * 0.125f, l0);
    h1 = bfpack(a.z * 0.125f, a.w * 0.125f, l1);
    *(uint2*)&gQh[base] = make_uint2(h0, h1);
    *(uint2*)&gQl[base] = make_uint2(l0, l1);

    a = *(const float4*)(k + base);
    h0 = bfpack(a.x, a.y, l0);
    h1 = bfpack(a.z, a.w, l1);
    *(uint2*)&gKh[base] = make_uint2(h0, h1);
    *(uint2*)&gKl[base] = make_uint2(l0, l1);

    a = *(const float4*)(v + base);
    h0 = bfpack(a.x, a.y, l0);
    h1 = bfpack(a.z, a.w, l1);
    *(uint2*)&gVh[base] = make_uint2(h0, h1);
    *(uint2*)&gVl[base] = make_uint2(l0, l1);
}

// ---------------------------------------------------------------------------
// Kernel A: raw scores + softmax stats. cp.async 2-stage pipeline.
// Block: 32(q) x 32(k-tile), 128 threads, 4 warps as 2(m) x 2(n).
// Q fragments hoisted out of the k-loop.
// ---------------------------------------------------------------------------
__global__ __launch_bounds__(128) void scores_kernel(
    const float* __restrict__ dq, const float* __restrict__ rt,
    const float* __restrict__ rb, float* __restrict__ scores) {
    __shared__ __align__(16) __nv_bfloat16 Qh[32][72], Ql[32][72];
    __shared__ __align__(16) __nv_bfloat16 Kh[2][32][72], Kl[2][32][72];
    __shared__ __align__(16) float Xs[2][32][12];
    __shared__ float Dq[32][4];
    __shared__ float SredM[4][16], SredS[4][16];

    const int h = blockIdx.y, qt = blockIdx.x * 32;
    const int t = threadIdx.x, lane = t & 31, warp = t >> 5;
    const int m0 = (warp >> 1) * 16, n0 = (warp & 1) * 16;

    // issue preload of K tile 0
#pragma unroll
    for (int j = 0; j < 2; j++) {
        int i = t + j * 128;
        int r = i >> 3, cc = (i & 7) * 8;
        size_t g = ((size_t)h * LL + r) * DD + cc;
        cp16(&Kh[0][r][cc], &gKh[g]);
        cp16(&Kl[0][r][cc], &gKl[g]);
    }
    if (t < 96) cp16(&Xs[0][t / 3][(t % 3) * 4], &g_xy[h][t / 3][(t % 3) * 4]);
    cp_commit();

    // Q tile from preconverted arrays (plain loads)
    for (int i = t; i < 32 * 8; i += 128) {
        int r = i >> 3, c8 = (i & 7) * 8;
        size_t g = ((size_t)h * LL + qt + r) * DD + c8;
        *(uint4*)&Qh[r][c8] = *(const uint4*)&gQh[g];
        *(uint4*)&Ql[r][c8] = *(const uint4*)&gQl[g];
    }
    for (int i = t; i < 32 * 3; i += 128) Dq[i / 3][i % 3] = dq[(qt + i / 3) * 3 + i % 3];
    __syncthreads();

    // Hoist Q fragments (invariant over k-loop): 4 k-steps x (hi,lo)
    uint32_t qh[4][4], ql[4][4];
#pragma unroll
    for (int s = 0; s < 4; s++) {
        int ar = m0 + (lane & 15), ac = s * 16 + (lane >> 4) * 8;
        ldsm_x4(smem_u32(&Qh[ar][ac]), qh[s][0], qh[s][1], qh[s][2], qh[s][3]);
        ldsm_x4(smem_u32(&Ql[ar][ac]), ql[s][0], ql[s][1], ql[s][2], ql[s][3]);
    }

    const int r0l = m0 + (lane >> 2), r1l = r0l + 8;
    const float da0 = Dq[r0l][0], da1 = Dq[r0l][1], da2 = Dq[r0l][2];
    const float db0 = Dq[r1l][0], db1 = Dq[r1l][1], db2 = Dq[r1l][2];
    const int qg0 = qt + r0l, qg1 = qt + r1l;

    float m0r = -1e30f, s0r = 0.f, m1r = -1e30f, s1r = 0.f;

    for (int ti = 0; ti < 64; ti++) {
        const int cur = ti & 1, kt = ti * 32;
        if (ti < 63) {
            int nb = cur ^ 1, nkt = kt + 32;
#pragma unroll
            for (int j = 0; j < 2; j++) {
                int i = t + j * 128;
                int r = i >> 3, cc = (i & 7) * 8;
                size_t g = ((size_t)h * LL + nkt + r) * DD + cc;
                cp16(&Kh[nb][r][cc], &gKh[g]);
                cp16(&Kl[nb][r][cc], &gKl[g]);
            }
            if (t < 96) cp16(&Xs[nb][t / 3][(t % 3) * 4], &g_xy[h][nkt + t / 3][(t % 3) * 4]);
            cp_commit();
            cp_wait1();
        } else {
            cp_wait0();
        }
        __syncthreads();

        // prefetch rt/rb for this tile's epilogue
        float2 prtA[2], prbA[2], prtB[2], prbB[2];
#pragma unroll
        for (int nt = 0; nt < 2; nt++) {
            int kg = kt + n0 + nt * 8 + (lane & 3) * 2;
            prtA[nt] = *(const float2*)(rt + (size_t)qg0 * LL + kg);
            prbA[nt] = *(const float2*)(rb + (size_t)qg0 * LL + kg);
            prtB[nt] = *(const float2*)(rt + (size_t)qg1 * LL + kg);
            prbB[nt] = *(const float2*)(rb + (size_t)qg1 * LL + kg);
        }

        float acc[2][4];
#pragma unroll
        for (int nt = 0; nt < 2; nt++)
#pragma unroll
            for (int j = 0; j < 4; j++) acc[nt][j] = 0.f;

#pragma unroll
        for (int s = 0; s < 4; s++) {
#pragma unroll
            for (int nt = 0; nt < 2; nt++) {
                uint32_t bh[2], bl[2];
                int br = n0 + nt * 8 + (lane & 7);
                int bc = s * 16 + ((lane >> 3) & 1) * 8;
                ldsm_x2(smem_u32(&Kh[cur][br][bc]), bh[0], bh[1]);
                ldsm_x2(smem_u32(&Kl[cur][br][bc]), bl[0], bl[1]);
                mma16816(acc[nt], qh[s], bh);
                mma16816(acc[nt], qh[s], bl);
                mma16816(acc[nt], ql[s], bh);
            }
        }

        // Epilogue: bias + softplus gate + write + stats
        float v0[4], v1[4];
#pragma unroll
        for (int nt = 0; nt < 2; nt++) {
            int kc = n0 + nt * 8 + (lane & 3) * 2;
            int kg = kt + kc;
            float4 xa0 = *(const float4*)&Xs[cur][kc][0];
            float4 xa1 = *(const float4*)&Xs[cur][kc][4];
            float4 xa2 = *(const float4*)&Xs[cur][kc][8];
            float4 xb0 = *(const float4*)&Xs[cur][kc + 1][0];
            float4 xb1 = *(const float4*)&Xs[cur][kc + 1][4];
            float4 xb2 = *(const float4*)&Xs[cur][kc + 1][8];

            float s00 = bias_apply(acc[nt][0], da0, da1, da2, prtA[nt].x, prbA[nt].x, xa0, xa1, xa2);
            float s01 = bias_apply(acc[nt][1], da0, da1, da2, prtA[nt].y, prbA[nt].y, xb0, xb1, xb2);
            float s10 = bias_apply(acc[nt][2], db0, db1, db2, prtB[nt].x, prbB[nt].x, xa0, xa1, xa2);
            float s11 = bias_apply(acc[nt][3], db0, db1, db2, prtB[nt].y, prbB[nt].y, xb0, xb1, xb2);

            v0[nt * 2] = s00; v0[nt * 2 + 1] = s01;
            v1[nt * 2] = s10; v1[nt * 2 + 1] = s11;

            *(float2*)(scores + ((size_t)(h * LL) + qg0) * LL + kg) = make_float2(s00, s01);
            *(float2*)(scores + ((size_t)(h * LL) + qg1) * LL + kg) = make_float2(s10, s11);
        }

        float tm0 = fmaxf(fmaxf(v0[0], v0[1]), fmaxf(v0[2], v0[3]));
        float tm1 = fmaxf(fmaxf(v1[0], v1[1]), fmaxf(v1[2], v1[3]));
        float nm0 = fmaxf(m0r, tm0), nm1 = fmaxf(m1r, tm1);
        float ad0 = 0.f, ad1 = 0.f;
#pragma unroll
        for (int j = 0; j < 4; j++) {
            ad0 += __expf(v0[j] - nm0);
            ad1 += __expf(v1[j] - nm1);
        }
        s0r = s0r * __expf(m0r - nm0) + ad0; m0r = nm0;
        s1r = s1r * __expf(m1r - nm1) + ad1; m1r = nm1;

        __syncthreads();
    }

    // Stats reduction: across lane&3 group, then warp pairs (same m0)
#pragma unroll
    for (int off = 1; off <= 2; off <<= 1) {
        float om = __shfl_xor_sync(0xffffffffu, m0r, off);
        float os = __shfl_xor_sync(0xffffffffu, s0r, off);
        float nm = fmaxf(m0r, om);
        s0r = s0r * __expf(m0r - nm) + os * __expf(om - nm);
        m0r = nm;
        om = __shfl_xor_sync(0xffffffffu, m1r, off);
        os = __shfl_xor_sync(0xffffffffu, s1r, off);
        nm = fmaxf(m1r, om);
        s1r = s1r * __expf(m1r - nm) + os * __expf(om - nm);
        m1r = nm;
    }
    if ((lane & 3) == 0) {
        int lr = lane >> 2;
        SredM[warp][lr] = m0r;     SredS[warp][lr] = s0r;
        SredM[warp][8 + lr] = m1r; SredS[warp][8 + lr] = s1r;
    }
    __syncthreads();
    if (t < 32) {
        int wp = t >> 4, loc = t & 15;
        float mA = SredM[2 * wp][loc], sA = SredS[2 * wp][loc];
        float mB = SredM[2 * wp + 1][loc], sB = SredS[2 * wp + 1][loc];
        float nm = fmaxf(mA, mB);
        float ss = sA * __expf(mA - nm) + sB * __expf(mB - nm);
        g_stats[h][qt + t] = make_float2(nm, 1.f / ss);
    }
}

// ---------------------------------------------------------------------------
// Kernel C: fused softmax + PV, P entirely in registers.
// Block: 64(q) x 64(d), 128 threads, 4 warps each owning m16 x n64.
// cp.async double-buffered V, register-prefetched scores, x4-trans V ldsm.
// ---------------------------------------------------------------------------
__global__ __launch_bounds__(128) void smpv_kernel(const float* __restrict__ c,
                                                   float* __restrict__ probs,
                                                   float* __restrict__ out) {
    __shared__ __align__(16) __nv_bfloat16 Vh[2][64][72], Vl[2][64][72];
    __shared__ __align__(16) float Cs[2048];

    const int h = blockIdx.y, qt = blockIdx.x * 64;
    const int t = threadIdx.x, lane = t & 31, warp = t >> 5;
    const int c0 = (lane & 3) * 2;
    const int r0 = qt + warp * 16 + (lane >> 2);

    float* sp0 = probs + ((size_t)h * LL + r0) * LL;
    float* sp1 = sp0 + 8 * LL;  // row r0+8

    const float2 st0 = g_stats[h][r0];
    const float2 st1 = g_stats[h][r0 + 8];

    // V tile 0 preload: 64 rows x 64 cols = 512 cp16 per array
#pragma unroll
    for (int j = 0; j < 4; j++) {
        int i = t + j * 128;
        int r = i >> 3, ce = (i & 7) * 8;
        size_t g = ((size_t)h * LL + r) * DD + ce;
        cp16(&Vh[0][r][ce], &gVh[g]);
        cp16(&Vl[0][r][ce], &gVl[g]);
    }
    cp_commit();

    // c -> smem
    for (int i = t; i < 512; i += 128)
        *(float4*)&Cs[i * 4] = *(const float4*)(c + i * 4);

    // prefetch scores tile 0
    float2 pre[16];
#pragma unroll
    for (int s = 0; s < 4; s++) {
        int col = s * 16 + c0;
        pre[s * 4 + 0] = *(const float2*)(sp0 + col);
        pre[s * 4 + 1] = *(const float2*)(sp1 + col);
        pre[s * 4 + 2] = *(const float2*)(sp0 + col + 8);
        pre[s * 4 + 3] = *(const float2*)(sp1 + col + 8);
    }

    float acc[8][4];
#pragma unroll
    for (int nt = 0; nt < 8; nt++)
#pragma unroll
        for (int j = 0; j < 4; j++) acc[nt][j] = 0.f;

    for (int ti = 0; ti < 32; ti++) {
        const int cur = ti & 1, kt = ti * 64;
        if (ti < 31) {
            int nb = cur ^ 1, nkt = kt + 64;
#pragma unroll
            for (int j = 0; j < 4; j++) {
                int i = t + j * 128;
                int r = i >> 3, ce = (i & 7) * 8;
                size_t g = ((size_t)h * LL + nkt + r) * DD + ce;
                cp16(&Vh[nb][r][ce], &gVh[g]);
                cp16(&Vl[nb][r][ce], &gVl[g]);
            }
            cp_commit();
            cp_wait1();
        } else {
            cp_wait0();
        }
        __syncthreads();

        // transform prefetched scores -> probs writes + A fragments
        uint32_t AH[4][4], AL[4][4];
#pragma unroll
        for (int s = 0; s < 4; s++) {
            int col = kt + s * 16 + c0;
            float2 cA = *(const float2*)&Cs[col];
            float2 cB = *(const float2*)&Cs[col + 8];
            float p00 = __expf(pre[s * 4 + 0].x - st0.x) * st0.y * cA.x;
            float p01 = __expf(pre[s * 4 + 0].y - st0.x) * st0.y * cA.y;
            float p10 = __expf(pre[s * 4 + 1].x - st1.x) * st1.y * cA.x;
            float p11 = __expf(pre[s * 4 + 1].y - st1.x) * st1.y * cA.y;
            float p20 = __expf(pre[s * 4 + 2].x - st0.x) * st0.y * cB.x;
            float p21 = __expf(pre[s * 4 + 2].y - st0.x) * st0.y * cB.y;
            float p30 = __expf(pre[s * 4 + 3].x - st1.x) * st1.y * cB.x;
            float p31 = __expf(pre[s * 4 + 3].y - st1.x) * st1.y * cB.y;

            *(float2*)(sp0 + col)     = make_float2(p00, p01);
            *(float2*)(sp1 + col)     = make_float2(p10, p11);
            *(float2*)(sp0 + col + 8) = make_float2(p20, p21);
            *(float2*)(sp1 + col + 8) = make_float2(p30, p31);

            AH[s][0] = bfpack(p00, p01, AL[s][0]);
            AH[s][1] = bfpack(p10, p11, AL[s][1]);
            AH[s][2] = bfpack(p20, p21, AL[s][2]);
            AH[s][3] = bfpack(p30, p31, AL[s][3]);
        }

        // prefetch scores for next tile (hidden under MMAs)
        if (ti < 31) {
            int nkt = kt + 64;
#pragma unroll
            for (int s = 0; s < 4; s++) {
                int col = nkt + s * 16 + c0;
                pre[s * 4 + 0] = *(const float2*)(sp0 + col);
                pre[s * 4 + 1] = *(const float2*)(sp1 + col);
                pre[s * 4 + 2] = *(const float2*)(sp0 + col + 8);
                pre[s * 4 + 3] = *(const float2*)(sp1 + col + 8);
            }
        }

        // MMAs: m16 x n64 per warp; V fragments via x4 trans (2 nt per ldsm)
#pragma unroll
        for (int s = 0; s < 4; s++) {
            int vr4 = s * 16 + (lane & 7) + ((lane >> 3) & 1) * 8;
#pragma unroll
            for (int nt2 = 0; nt2 < 4; nt2++) {
                int vc4 = nt2 * 16 + ((lane >> 4) & 1) * 8;
                uint32_t bh4[4], bl4[4];
                ldsm_x4t(smem_u32(&Vh[cur][vr4][vc4]), bh4[0], bh4[1], bh4[2], bh4[3]);
                ldsm_x4t(smem_u32(&Vl[cur][vr4][vc4]), bl4[0], bl4[1], bl4[2], bl4[3]);
                mma16816(acc[nt2 * 2 + 0], AH[s], &bh4[0]);
                mma16816(acc[nt2 * 2 + 0], AH[s], &bl4[0]);
                mma16816(acc[nt2 * 2 + 0], AL[s], &bh4[0]);
                mma16816(acc[nt2 * 2 + 1], AH[s], &bh4[2]);
                mma16816(acc[nt2 * 2 + 1], AH[s], &bl4[2]);
                mma16816(acc[nt2 * 2 + 1], AL[s], &bh4[2]);
            }
        }
        __syncthreads();
    }

    // Output: 16 rows x 64 cols per warp
#pragma unroll
    for (int nt = 0; nt < 8; nt++) {
        int dc = nt * 8 + c0;
        *(float2*)(out + ((size_t)h * LL + r0) * DD + dc) =
            make_float2(acc[nt][0], acc[nt][1]);
        *(float2*)(out + ((size_t)h * LL + r0 + 8) * DD + dc) =
            make_float2(acc[nt][2], acc[nt][3]);
    }
}

// ---------------------------------------------------------------------------
extern "C" void kernel_launch(void* const* d_in, const int* in_sizes, int n_in,
                              void* d_out, int out_size) {
    const float* q   = (const float*)d_in[0];
    const float* k   = (const float*)d_in[1];
    const float* v   = (const float*)d_in[2];
    const float* c   = (const float*)d_in[3];
    const float* dq  = (const float*)d_in[4];
    const float* dkt = (const float*)d_in[5];
    const float* dkb = (const float*)d_in[6];
    const float* dks = (const float*)d_in[7];
    const float* rt  = (const float*)d_in[8];
    const float* rb  = (const float*)d_in[9];
    const float* Ww  = (const float*)d_in[10];
    const float* Wb  = (const float*)d_in[11];

    float* out   = (float*)d_out;                        // [H, L, D]
    float* probs = (float*)d_out + (size_t)HH * LL * DD; // [H, L, L]

    prep_kernel<<<(HH * LL) / 256, 256>>>(dkt, dkb, dks, Ww, Wb);
    conv_kernel<<<(HH * LL * DD) / (256 * 4), 256>>>(q, k, v);

    dim3 gridA(LL / 32, HH);
    scores_kernel<<<gridA, 128>>>(dq, rt, rb, probs);

    dim3 gridC(LL / 64, HH);
    smpv_kernel<<<gridC, 128>>>(c, probs, out);
}